// round 6
// baseline (speedup 1.0000x reference)
#include <cuda_runtime.h>

#define BB 4
#define LQ 512
#define LK 512
#define HH 256

#define CTX_ELEMS (BB*LQ*HH)
#define LOG2E2 2.885390081777927f   // 2*log2(e)

static __device__ float g_q [BB*LQ*HH];     // Eq = exp(2*q_proj), [b][q][h]
static __device__ float g_kT[BB*HH*LK];     // Ek = exp(2*k_proj), TRANSPOSED [b][h][k]
static __device__ float g_s [BB*LQ*LK];     // raw scores; ref score = C - 2s (consts drop)

typedef unsigned long long ull;

__device__ __forceinline__ float ex2a(float x) {
    float e; asm("ex2.approx.ftz.f32 %0, %1;" : "=f"(e) : "f"(x)); return e;
}
__device__ __forceinline__ float rcpa(float x) {
    float r; asm("rcp.approx.ftz.f32 %0, %1;" : "=f"(r) : "f"(x)); return r;
}
// packed f32x2 helpers (Blackwell FFMA2 path — PTX only)
__device__ __forceinline__ ull pk(float x, float y) {
    ull r; asm("mov.b64 %0, {%1, %2};" : "=l"(r) : "f"(x), "f"(y)); return r;
}
__device__ __forceinline__ void upk(ull v, float& x, float& y) {
    asm("mov.b64 {%0, %1}, %2;" : "=f"(x), "=f"(y) : "l"(v));
}
__device__ __forceinline__ ull fma2(ull a, ull b, ull c) {
    ull d; asm("fma.rn.f32x2 %0, %1, %2, %3;" : "=l"(d) : "l"(a), "l"(b), "l"(c)); return d;
}
__device__ __forceinline__ ull mul2(ull a, ull b) {
    ull d; asm("mul.rn.f32x2 %0, %1, %2;" : "=l"(d) : "l"(a), "l"(b)); return d;
}
// 64-bit smem load: lands directly in an aligned register pair (no MOVs)
__device__ __forceinline__ ull lds2(const float* p) {
    return __double_as_longlong(*(const double*)p);
}

// ---------------------------------------------------------------------------
// K1: projections + exp epilogue. Double-buffered smem + register prefetch.
// z=0: g_q[b][q][h] = exp(2*(q@WqT+bq));  z=1: g_kT[b][h][k] (transposed!)
// ---------------------------------------------------------------------------
__global__ __launch_bounds__(256) void proj_kernel(
    const float* __restrict__ query, const float* __restrict__ values,
    const float* __restrict__ Wq, const float* __restrict__ bq,
    const float* __restrict__ Wk, const float* __restrict__ bk)
{
    const float* in   = blockIdx.z ? values : query;
    const float* W    = blockIdx.z ? Wk : Wq;
    const float* bias = blockIdx.z ? bk : bq;

    __shared__ float As[2][32][68];
    __shared__ float Bs[2][32][68];

    int tid = threadIdx.x;
    int tx = tid & 15, ty = tid >> 4;
    int m0 = blockIdx.x * 64, n0 = blockIdx.y * 64;

    int row0 = tid >> 3,         c40 = tid & 7;
    int row1 = (tid + 256) >> 3, c41 = (tid + 256) & 7;

    float4 ra0, ra1, rb0, rb1;
    ra0 = *(const float4*)&in[(size_t)(m0 + row0) * HH + c40 * 4];
    rb0 = *(const float4*)&W [(size_t)(n0 + row0) * HH + c40 * 4];
    ra1 = *(const float4*)&in[(size_t)(m0 + row1) * HH + c41 * 4];
    rb1 = *(const float4*)&W [(size_t)(n0 + row1) * HH + c41 * 4];

    As[0][c40*4+0][row0] = ra0.x; As[0][c40*4+1][row0] = ra0.y;
    As[0][c40*4+2][row0] = ra0.z; As[0][c40*4+3][row0] = ra0.w;
    Bs[0][c40*4+0][row0] = rb0.x; Bs[0][c40*4+1][row0] = rb0.y;
    Bs[0][c40*4+2][row0] = rb0.z; Bs[0][c40*4+3][row0] = rb0.w;
    As[0][c41*4+0][row1] = ra1.x; As[0][c41*4+1][row1] = ra1.y;
    As[0][c41*4+2][row1] = ra1.z; As[0][c41*4+3][row1] = ra1.w;
    Bs[0][c41*4+0][row1] = rb1.x; Bs[0][c41*4+1][row1] = rb1.y;
    Bs[0][c41*4+2][row1] = rb1.z; Bs[0][c41*4+3][row1] = rb1.w;
    __syncthreads();

    float acc[4][4] = {};
    int buf = 0;

    #pragma unroll 1
    for (int it = 0; it < HH / 32; it++) {
        int k1 = (it + 1) * 32;
        bool more = (it + 1 < HH / 32);
        if (more) {
            ra0 = *(const float4*)&in[(size_t)(m0 + row0) * HH + k1 + c40 * 4];
            rb0 = *(const float4*)&W [(size_t)(n0 + row0) * HH + k1 + c40 * 4];
            ra1 = *(const float4*)&in[(size_t)(m0 + row1) * HH + k1 + c41 * 4];
            rb1 = *(const float4*)&W [(size_t)(n0 + row1) * HH + k1 + c41 * 4];
        }
        #pragma unroll 8
        for (int kk = 0; kk < 32; kk++) {
            float4 a = *(const float4*)&As[buf][kk][ty * 4];
            float4 b = *(const float4*)&Bs[buf][kk][tx * 4];
            float av[4] = {a.x, a.y, a.z, a.w};
            float bv[4] = {b.x, b.y, b.z, b.w};
            #pragma unroll
            for (int i = 0; i < 4; i++)
                #pragma unroll
                for (int j = 0; j < 4; j++)
                    acc[i][j] = fmaf(av[i], bv[j], acc[i][j]);
        }
        if (more) {
            int nb = buf ^ 1;
            As[nb][c40*4+0][row0] = ra0.x; As[nb][c40*4+1][row0] = ra0.y;
            As[nb][c40*4+2][row0] = ra0.z; As[nb][c40*4+3][row0] = ra0.w;
            Bs[nb][c40*4+0][row0] = rb0.x; Bs[nb][c40*4+1][row0] = rb0.y;
            Bs[nb][c40*4+2][row0] = rb0.z; Bs[nb][c40*4+3][row0] = rb0.w;
            As[nb][c41*4+0][row1] = ra1.x; As[nb][c41*4+1][row1] = ra1.y;
            As[nb][c41*4+2][row1] = ra1.z; As[nb][c41*4+3][row1] = ra1.w;
            Bs[nb][c41*4+0][row1] = rb1.x; Bs[nb][c41*4+1][row1] = rb1.y;
            Bs[nb][c41*4+2][row1] = rb1.z; Bs[nb][c41*4+3][row1] = rb1.w;
        }
        __syncthreads();
        buf ^= 1;
    }

    if (blockIdx.z == 0) {
        #pragma unroll
        for (int i = 0; i < 4; i++)
            #pragma unroll
            for (int j = 0; j < 4; j++) {
                int m = m0 + ty * 4 + i;
                int n = n0 + tx * 4 + j;
                g_q[(size_t)m * HH + n] = ex2a((acc[i][j] + bias[n]) * LOG2E2);
            }
    } else {
        int b    = m0 / LK;
        int mloc = (m0 % LK) + ty * 4;
        #pragma unroll
        for (int j = 0; j < 4; j++) {
            int n = n0 + tx * 4 + j;
            float4 v;
            v.x = ex2a((acc[0][j] + bias[n]) * LOG2E2);
            v.y = ex2a((acc[1][j] + bias[n]) * LOG2E2);
            v.z = ex2a((acc[2][j] + bias[n]) * LOG2E2);
            v.w = ex2a((acc[3][j] + bias[n]) * LOG2E2);
            *(float4*)&g_kT[((size_t)b * HH + n) * LK + mloc] = v;
        }
    }
}

// ---------------------------------------------------------------------------
// K2: scores, packed f32x2, quad-rcp over h, 4 k per thread (2 packed pairs
// -> two independent quad-trees per step for ILP). ek pairs loaded from smem
// as 64-bit (LDS.64 direct to register pair, no MOVs).
// Thread = (qrow 0..15, hc 0..15); owns h = hc + 16j, j=0..15.
// Block tile: 32 q (2 passes) x 64 k (2 staged subtiles of 32 k).
// eks pitch 34 floats (136B): 8B-aligned rows, hc*... -> conflict-free LDS.64
// with 2-way broadcast.
// ---------------------------------------------------------------------------
__global__ __launch_bounds__(256) void score_kernel(const float* __restrict__ We)
{
    __shared__ float eks[256][34];   // 34 KB

    int b   = blockIdx.z;
    int q0  = blockIdx.x * 32;
    int k0  = blockIdx.y * 64;
    int tid = threadIdx.x;
    int qrow = tid >> 4;     // 0..15
    int hc   = tid & 15;     // 0..15

    const ull ONE2 = pk(1.0f, 1.0f);

    ull wep[16];
    #pragma unroll
    for (int j = 0; j < 16; j++) {
        float w = We[hc + 16 * j];
        wep[j] = pk(w, w);
    }

    #pragma unroll 1
    for (int st = 0; st < 2; st++) {
        int kb = k0 + st * 32;
        __syncthreads();
        {
            const float* src = g_kT + ((size_t)(b * HH) + tid) * LK + kb;
            #pragma unroll
            for (int c = 0; c < 8; c++) {
                float4 v = *(const float4*)&src[c * 4];
                *(float2*)&eks[tid][c * 4]     = make_float2(v.x, v.y);
                *(float2*)&eks[tid][c * 4 + 2] = make_float2(v.z, v.w);
            }
        }
        __syncthreads();

        #pragma unroll 1
        for (int qp = 0; qp < 2; qp++) {
            int q = q0 + qp * 16 + qrow;
            ull eqp[16];
            {
                const float* eqb = g_q + ((size_t)(b * LQ) + q) * HH;
                #pragma unroll
                for (int j = 0; j < 16; j++) {
                    float e = eqb[hc + 16 * j];
                    eqp[j] = pk(e, e);
                }
            }
            float* srow = g_s + ((size_t)(b * LQ) + q) * LK + kb;

            #pragma unroll 2
            for (int kp = 0; kp < 8; kp++) {     // 4 k columns per iter
                ull accA = pk(0.0f, 0.0f);
                ull accB = pk(0.0f, 0.0f);
                #pragma unroll
                for (int jq = 0; jq < 4; jq++) {
                    int h0 = hc + 16 * (4 * jq);
                    // tree A: k pair {4kp, 4kp+1}
                    ull eA0 = lds2(&eks[h0     ][4 * kp]);
                    ull eA1 = lds2(&eks[h0 + 16][4 * kp]);
                    ull eA2 = lds2(&eks[h0 + 32][4 * kp]);
                    ull eA3 = lds2(&eks[h0 + 48][4 * kp]);
                    // tree B: k pair {4kp+2, 4kp+3}
                    ull eB0 = lds2(&eks[h0     ][4 * kp + 2]);
                    ull eB1 = lds2(&eks[h0 + 16][4 * kp + 2]);
                    ull eB2 = lds2(&eks[h0 + 32][4 * kp + 2]);
                    ull eB3 = lds2(&eks[h0 + 48][4 * kp + 2]);

                    ull tA0 = fma2(eA0, eqp[4*jq+0], ONE2);
                    ull tB0 = fma2(eB0, eqp[4*jq+0], ONE2);
                    ull tA1 = fma2(eA1, eqp[4*jq+1], ONE2);
                    ull tB1 = fma2(eB1, eqp[4*jq+1], ONE2);
                    ull tA2 = fma2(eA2, eqp[4*jq+2], ONE2);
                    ull tB2 = fma2(eB2, eqp[4*jq+2], ONE2);
                    ull tA3 = fma2(eA3, eqp[4*jq+3], ONE2);
                    ull tB3 = fma2(eB3, eqp[4*jq+3], ONE2);

                    ull dA01 = mul2(tA0, tA1), dB01 = mul2(tB0, tB1);
                    ull dA23 = mul2(tA2, tA3), dB23 = mul2(tB2, tB3);
                    ull nA01 = fma2(wep[4*jq+0], tA1, mul2(wep[4*jq+1], tA0));
                    ull nB01 = fma2(wep[4*jq+0], tB1, mul2(wep[4*jq+1], tB0));
                    ull nA23 = fma2(wep[4*jq+2], tA3, mul2(wep[4*jq+3], tA2));
                    ull nB23 = fma2(wep[4*jq+2], tB3, mul2(wep[4*jq+3], tB2));
                    ull nAQ  = fma2(nA01, dA23, mul2(nA23, dA01));
                    ull nBQ  = fma2(nB01, dB23, mul2(nB23, dB01));
                    ull dAQ  = mul2(dA01, dA23);
                    ull dBQ  = mul2(dB01, dB23);
                    float da0, da1, db0, db1;
                    upk(dAQ, da0, da1);
                    upk(dBQ, db0, db1);
                    accA = fma2(nAQ, pk(rcpa(da0), rcpa(da1)), accA);
                    accB = fma2(nBQ, pk(rcpa(db0), rcpa(db1)), accB);
                }
                float a0, a1, a2, a3;
                upk(accA, a0, a1);
                upk(accB, a2, a3);
                #pragma unroll
                for (int o = 1; o < 16; o <<= 1) {
                    a0 += __shfl_xor_sync(0xffffffffu, a0, o);
                    a1 += __shfl_xor_sync(0xffffffffu, a1, o);
                    a2 += __shfl_xor_sync(0xffffffffu, a2, o);
                    a3 += __shfl_xor_sync(0xffffffffu, a3, o);
                }
                if (hc == 0)
                    *(float4*)&srow[4 * kp] = make_float4(a0, a1, a2, a3);
            }
        }
    }
}

// ---------------------------------------------------------------------------
// K2b: softmax over k of score = -2*s. Warp per row.
// ---------------------------------------------------------------------------
__global__ __launch_bounds__(256) void softmax_kernel(float* __restrict__ attn)
{
    int row  = blockIdx.x * 8 + (threadIdx.x >> 5);
    int lane = threadIdx.x & 31;
    const float* s = g_s + (size_t)row * LK;

    float vals[16];
    float m = -1e30f;
    #pragma unroll
    for (int i = 0; i < 16; i++) {
        vals[i] = -2.0f * s[lane + 32 * i];
        m = fmaxf(m, vals[i]);
    }
    #pragma unroll
    for (int o = 16; o; o >>= 1) m = fmaxf(m, __shfl_xor_sync(0xffffffffu, m, o));
    float sum = 0.0f;
    #pragma unroll
    for (int i = 0; i < 16; i++) {
        vals[i] = ex2a((vals[i] - m) * 1.4426950408889634f);
        sum += vals[i];
    }
    #pragma unroll
    for (int o = 16; o; o >>= 1) sum += __shfl_xor_sync(0xffffffffu, sum, o);
    float inv = 1.0f / sum;

    float* arow = attn + (size_t)row * LK;
    #pragma unroll
    for (int i = 0; i < 16; i++)
        arow[lane + 32 * i] = vals[i] * inv;
}

// ---------------------------------------------------------------------------
// K3: context = attn @ values, NO split-K. Tile 32(M)x64(N), BK=32,
// 256 threads, 2x4 reg tile, double-buffered + register prefetch.
// Grid 16 x 4 x 4 = 256 blocks -> all SMs busy, direct ctx write.
// ---------------------------------------------------------------------------
__global__ __launch_bounds__(256) void context_kernel(
    const float* __restrict__ values, const float* __restrict__ attn,
    float* __restrict__ ctx)
{
    __shared__ float As[2][32][36];   // [k][m] transposed
    __shared__ float Vs[2][32][68];   // [k][n]

    int tid = threadIdx.x;
    int b  = blockIdx.z;
    int q0 = blockIdx.x * 32;
    int n0 = blockIdx.y * 64;
    int tx = tid & 15, ty = tid >> 4;

    const float* Abase = attn + (size_t)b * LQ * LK;
    const float* Vbase = values + (size_t)b * LK * HH;

    int arow = tid >> 3,        ac4 = tid & 7;       // 32 rows x 8 float4
    int vk0 = tid >> 4,         vc40 = tid & 15;
    int vk1 = (tid + 256) >> 4, vc41 = (tid + 256) & 15;

    float4 ra, rv0, rv1;
    ra  = *(const float4*)&Abase[(size_t)(q0 + arow) * LK + ac4 * 4];
    rv0 = *(const float4*)&Vbase[(size_t)vk0 * HH + n0 + vc40 * 4];
    rv1 = *(const float4*)&Vbase[(size_t)vk1 * HH + n0 + vc41 * 4];

    As[0][ac4*4+0][arow] = ra.x; As[0][ac4*4+1][arow] = ra.y;
    As[0][ac4*4+2][arow] = ra.z; As[0][ac4*4+3][arow] = ra.w;
    *(float4*)&Vs[0][vk0][vc40 * 4] = rv0;
    *(float4*)&Vs[0][vk1][vc41 * 4] = rv1;
    __syncthreads();

    float acc[2][4] = {};
    int buf = 0;

    #pragma unroll 1
    for (int it = 0; it < LK / 32; it++) {
        int k1 = (it + 1) * 32;
        bool more = (it + 1 < LK / 32);
        if (more) {
            ra  = *(const float4*)&Abase[(size_t)(q0 + arow) * LK + k1 + ac4 * 4];
            rv0 = *(const float4*)&Vbase[(size_t)(k1 + vk0) * HH + n0 + vc40 * 4];
            rv1 = *(const float4*)&Vbase[(size_t)(k1 + vk1) * HH + n0 + vc41 * 4];
        }
        #pragma unroll 8
        for (int kk = 0; kk < 32; kk++) {
            float2 a = *(const float2*)&As[buf][kk][ty * 2];
            float4 v = *(const float4*)&Vs[buf][kk][tx * 4];
            acc[0][0] = fmaf(a.x, v.x, acc[0][0]);
            acc[0][1] = fmaf(a.x, v.y, acc[0][1]);
            acc[0][2] = fmaf(a.x, v.z, acc[0][2]);
            acc[0][3] = fmaf(a.x, v.w, acc[0][3]);
            acc[1][0] = fmaf(a.y, v.x, acc[1][0]);
            acc[1][1] = fmaf(a.y, v.y, acc[1][1]);
            acc[1][2] = fmaf(a.y, v.z, acc[1][2]);
            acc[1][3] = fmaf(a.y, v.w, acc[1][3]);
        }
        if (more) {
            int nb = buf ^ 1;
            As[nb][ac4*4+0][arow] = ra.x; As[nb][ac4*4+1][arow] = ra.y;
            As[nb][ac4*4+2][arow] = ra.z; As[nb][ac4*4+3][arow] = ra.w;
            *(float4*)&Vs[nb][vk0][vc40 * 4] = rv0;
            *(float4*)&Vs[nb][vk1][vc41 * 4] = rv1;
        }
        __syncthreads();
        buf ^= 1;
    }

    #pragma unroll
    for (int i = 0; i < 2; i++) {
        float4 r = make_float4(acc[i][0], acc[i][1], acc[i][2], acc[i][3]);
        *(float4*)&ctx[(size_t)(b * LQ + q0 + ty * 2 + i) * HH + n0 + tx * 4] = r;
    }
}

// ---------------------------------------------------------------------------
// Launch: proj(+exp, K transposed) -> scores(f32x2) -> softmax -> context.
// Output layout: [context (B*LQ*H) | attention (B*LQ*LK)]. be unused.
// ---------------------------------------------------------------------------
extern "C" void kernel_launch(void* const* d_in, const int* in_sizes, int n_in,
                              void* d_out, int out_size)
{
    const float* query  = (const float*)d_in[0];
    const float* values = (const float*)d_in[1];
    const float* Wq     = (const float*)d_in[2];
    const float* bq     = (const float*)d_in[3];
    const float* Wk     = (const float*)d_in[4];
    const float* bk     = (const float*)d_in[5];
    const float* We     = (const float*)d_in[6];
    // d_in[7] = be, softmax-invariant

    float* out  = (float*)d_out;
    float* ctx  = out;
    float* attn = out + CTX_ELEMS;

    proj_kernel<<<dim3(32, 4, 2), 256>>>(query, values, Wq, bq, Wk, bk);
    score_kernel<<<dim3(LQ / 32, LK / 64, BB), 256>>>(We);
    softmax_kernel<<<dim3(BB * LQ / 8), 256>>>(attn);
    context_kernel<<<dim3(LQ / 32, HH / 64, BB), 256>>>(values, attn, ctx);
}

// round 7
// speedup vs baseline: 1.0741x; 1.0741x over previous
#include <cuda_runtime.h>

#define BB 4
#define LQ 512
#define LK 512
#define HH 256

#define CTX_ELEMS (BB*LQ*HH)
#define LOG2E2 2.885390081777927f   // 2*log2(e)

static __device__ float g_q [BB*LQ*HH];     // Eq = exp(2*q_proj), [b][q][h]
static __device__ float g_kT[BB*HH*LK];     // Ek = exp(2*k_proj), TRANSPOSED [b][h][k]
static __device__ float g_s [BB*LQ*LK];     // raw scores; ref score = C - 2s (consts drop)
static __device__ float g_part[2*CTX_ELEMS];// context split-K partials

typedef unsigned long long ull;

__device__ __forceinline__ float ex2a(float x) {
    float e; asm("ex2.approx.ftz.f32 %0, %1;" : "=f"(e) : "f"(x)); return e;
}
__device__ __forceinline__ float rcpa(float x) {
    float r; asm("rcp.approx.ftz.f32 %0, %1;" : "=f"(r) : "f"(x)); return r;
}
__device__ __forceinline__ ull pk(float x, float y) {
    ull r; asm("mov.b64 %0, {%1, %2};" : "=l"(r) : "f"(x), "f"(y)); return r;
}
__device__ __forceinline__ void upk(ull v, float& x, float& y) {
    asm("mov.b64 {%0, %1}, %2;" : "=f"(x), "=f"(y) : "l"(v));
}
__device__ __forceinline__ ull fma2(ull a, ull b, ull c) {
    ull d; asm("fma.rn.f32x2 %0, %1, %2, %3;" : "=l"(d) : "l"(a), "l"(b), "l"(c)); return d;
}
__device__ __forceinline__ ull mul2(ull a, ull b) {
    ull d; asm("mul.rn.f32x2 %0, %1, %2;" : "=l"(d) : "l"(a), "l"(b)); return d;
}
__device__ __forceinline__ ull lds2(const float* p) {
    return *(const ull*)p;
}

// ---------------------------------------------------------------------------
// K1: projections + exp epilogue. Double-buffered smem + register prefetch.
// z=0: g_q[b][q][h] = exp(2*(q@WqT+bq));  z=1: g_kT[b][h][k] (transposed!)
// ---------------------------------------------------------------------------
__global__ __launch_bounds__(256) void proj_kernel(
    const float* __restrict__ query, const float* __restrict__ values,
    const float* __restrict__ Wq, const float* __restrict__ bq,
    const float* __restrict__ Wk, const float* __restrict__ bk)
{
    const float* in   = blockIdx.z ? values : query;
    const float* W    = blockIdx.z ? Wk : Wq;
    const float* bias = blockIdx.z ? bk : bq;

    __shared__ float As[2][32][68];
    __shared__ float Bs[2][32][68];

    int tid = threadIdx.x;
    int tx = tid & 15, ty = tid >> 4;
    int m0 = blockIdx.x * 64, n0 = blockIdx.y * 64;

    int row0 = tid >> 3,         c40 = tid & 7;
    int row1 = (tid + 256) >> 3, c41 = (tid + 256) & 7;

    float4 ra0, ra1, rb0, rb1;
    ra0 = *(const float4*)&in[(size_t)(m0 + row0) * HH + c40 * 4];
    rb0 = *(const float4*)&W [(size_t)(n0 + row0) * HH + c40 * 4];
    ra1 = *(const float4*)&in[(size_t)(m0 + row1) * HH + c41 * 4];
    rb1 = *(const float4*)&W [(size_t)(n0 + row1) * HH + c41 * 4];

    As[0][c40*4+0][row0] = ra0.x; As[0][c40*4+1][row0] = ra0.y;
    As[0][c40*4+2][row0] = ra0.z; As[0][c40*4+3][row0] = ra0.w;
    Bs[0][c40*4+0][row0] = rb0.x; Bs[0][c40*4+1][row0] = rb0.y;
    Bs[0][c40*4+2][row0] = rb0.z; Bs[0][c40*4+3][row0] = rb0.w;
    As[0][c41*4+0][row1] = ra1.x; As[0][c41*4+1][row1] = ra1.y;
    As[0][c41*4+2][row1] = ra1.z; As[0][c41*4+3][row1] = ra1.w;
    Bs[0][c41*4+0][row1] = rb1.x; Bs[0][c41*4+1][row1] = rb1.y;
    Bs[0][c41*4+2][row1] = rb1.z; Bs[0][c41*4+3][row1] = rb1.w;
    __syncthreads();

    float acc[4][4] = {};
    int buf = 0;

    #pragma unroll 1
    for (int it = 0; it < HH / 32; it++) {
        int k1 = (it + 1) * 32;
        bool more = (it + 1 < HH / 32);
        if (more) {
            ra0 = *(const float4*)&in[(size_t)(m0 + row0) * HH + k1 + c40 * 4];
            rb0 = *(const float4*)&W [(size_t)(n0 + row0) * HH + k1 + c40 * 4];
            ra1 = *(const float4*)&in[(size_t)(m0 + row1) * HH + k1 + c41 * 4];
            rb1 = *(const float4*)&W [(size_t)(n0 + row1) * HH + k1 + c41 * 4];
        }
        #pragma unroll 8
        for (int kk = 0; kk < 32; kk++) {
            float4 a = *(const float4*)&As[buf][kk][ty * 4];
            float4 b = *(const float4*)&Bs[buf][kk][tx * 4];
            float av[4] = {a.x, a.y, a.z, a.w};
            float bv[4] = {b.x, b.y, b.z, b.w};
            #pragma unroll
            for (int i = 0; i < 4; i++)
                #pragma unroll
                for (int j = 0; j < 4; j++)
                    acc[i][j] = fmaf(av[i], bv[j], acc[i][j]);
        }
        if (more) {
            int nb = buf ^ 1;
            As[nb][c40*4+0][row0] = ra0.x; As[nb][c40*4+1][row0] = ra0.y;
            As[nb][c40*4+2][row0] = ra0.z; As[nb][c40*4+3][row0] = ra0.w;
            Bs[nb][c40*4+0][row0] = rb0.x; Bs[nb][c40*4+1][row0] = rb0.y;
            Bs[nb][c40*4+2][row0] = rb0.z; Bs[nb][c40*4+3][row0] = rb0.w;
            As[nb][c41*4+0][row1] = ra1.x; As[nb][c41*4+1][row1] = ra1.y;
            As[nb][c41*4+2][row1] = ra1.z; As[nb][c41*4+3][row1] = ra1.w;
            Bs[nb][c41*4+0][row1] = rb1.x; Bs[nb][c41*4+1][row1] = rb1.y;
            Bs[nb][c41*4+2][row1] = rb1.z; Bs[nb][c41*4+3][row1] = rb1.w;
        }
        __syncthreads();
        buf ^= 1;
    }

    if (blockIdx.z == 0) {
        #pragma unroll
        for (int i = 0; i < 4; i++)
            #pragma unroll
            for (int j = 0; j < 4; j++) {
                int m = m0 + ty * 4 + i;
                int n = n0 + tx * 4 + j;
                g_q[(size_t)m * HH + n] = ex2a((acc[i][j] + bias[n]) * LOG2E2);
            }
    } else {
        int b    = m0 / LK;
        int mloc = (m0 % LK) + ty * 4;
        #pragma unroll
        for (int j = 0; j < 4; j++) {
            int n = n0 + tx * 4 + j;
            float4 v;
            v.x = ex2a((acc[0][j] + bias[n]) * LOG2E2);
            v.y = ex2a((acc[1][j] + bias[n]) * LOG2E2);
            v.z = ex2a((acc[2][j] + bias[n]) * LOG2E2);
            v.w = ex2a((acc[3][j] + bias[n]) * LOG2E2);
            *(float4*)&g_kT[((size_t)b * HH + n) * LK + mloc] = v;
        }
    }
}

// ---------------------------------------------------------------------------
// K2: scores, packed f32x2 quad-rcp, h-contiguous thread ownership.
// Thread lane: hc = lane&15 owns h in [hc*16, hc*16+16); qh = lane>>4 picks
// one of 2 q rows per warp -> all eq/We global loads COALESCED (fixes the
// stride-16 gather that dominated R3-R6).
// eks smem is XOR-swizzled: ek(h, kpair) at [h][(kpair ^ (h>>4))*2], pitch
// 128B -> compute LDS.64 lanes hit banks (kp^hc)*2 = all 32 banks once
// (conflict-free), upper q-half broadcasts.
// Block tile: 32 q (2 passes) x 64 k (2 staged subtiles of 32 k).
// ---------------------------------------------------------------------------
__global__ __launch_bounds__(256) void score_kernel(const float* __restrict__ We)
{
    __shared__ float eks[256][32];   // 32 KB, swizzled

    int b  = blockIdx.z;
    int q0 = blockIdx.x * 32;
    int k0 = blockIdx.y * 64;
    int tid  = threadIdx.x;
    int lane = tid & 31;
    int hc   = lane & 15;
    int qh   = lane >> 4;
    int w    = tid >> 5;

    int s_kp = tid & 15;     // staging: kpair
    int s_hh = tid >> 4;     // staging: h mod 16

    const ull ONE2 = pk(1.0f, 1.0f);

    // We chunk (h = hc*16 .. +15), coalesced, packed once
    ull wep[16];
    {
        const float4* wp = (const float4*)(We + hc * 16);
        float4 w0 = wp[0], w1 = wp[1], w2 = wp[2], w3 = wp[3];
        wep[0]=pk(w0.x,w0.x); wep[1]=pk(w0.y,w0.y); wep[2]=pk(w0.z,w0.z); wep[3]=pk(w0.w,w0.w);
        wep[4]=pk(w1.x,w1.x); wep[5]=pk(w1.y,w1.y); wep[6]=pk(w1.z,w1.z); wep[7]=pk(w1.w,w1.w);
        wep[8]=pk(w2.x,w2.x); wep[9]=pk(w2.y,w2.y); wep[10]=pk(w2.z,w2.z); wep[11]=pk(w2.w,w2.w);
        wep[12]=pk(w3.x,w3.x); wep[13]=pk(w3.y,w3.y); wep[14]=pk(w3.z,w3.z); wep[15]=pk(w3.w,w3.w);
    }

    #pragma unroll 1
    for (int st = 0; st < 2; st++) {
        int kb = k0 + st * 32;
        __syncthreads();
        // stage 256h x 32k with XOR swizzle; global reads 128B-coalesced
        #pragma unroll
        for (int i = 0; i < 16; i++) {
            int h = s_hh + 16 * i;
            ull v = *(const ull*)(g_kT + ((size_t)(b * HH + h)) * LK + kb + 2 * s_kp);
            *(ull*)&eks[h][(s_kp ^ i) * 2] = v;
        }
        __syncthreads();

        #pragma unroll 1
        for (int qp = 0; qp < 2; qp++) {
            int q = q0 + qp * 16 + w * 2 + qh;
            // eq chunk, coalesced, packed
            ull eqp[16];
            {
                const float4* ep = (const float4*)(g_q + ((size_t)(b * LQ) + q) * HH + hc * 16);
                float4 e0 = ep[0], e1 = ep[1], e2 = ep[2], e3 = ep[3];
                eqp[0]=pk(e0.x,e0.x); eqp[1]=pk(e0.y,e0.y); eqp[2]=pk(e0.z,e0.z); eqp[3]=pk(e0.w,e0.w);
                eqp[4]=pk(e1.x,e1.x); eqp[5]=pk(e1.y,e1.y); eqp[6]=pk(e1.z,e1.z); eqp[7]=pk(e1.w,e1.w);
                eqp[8]=pk(e2.x,e2.x); eqp[9]=pk(e2.y,e2.y); eqp[10]=pk(e2.z,e2.z); eqp[11]=pk(e2.w,e2.w);
                eqp[12]=pk(e3.x,e3.x); eqp[13]=pk(e3.y,e3.y); eqp[14]=pk(e3.z,e3.z); eqp[15]=pk(e3.w,e3.w);
            }
            float* srow = g_s + ((size_t)(b * LQ) + q) * LK + kb;

            #pragma unroll 2
            for (int t = 0; t < 16; t++) {       // kpair t -> k = kb+2t, 2t+1
                int pc = (t ^ hc) * 2;           // swizzled column
                ull acc = pk(0.0f, 0.0f);
                #pragma unroll
                for (int jq = 0; jq < 4; jq++) {
                    const float* rb = &eks[16 * hc + 4 * jq][pc];
                    ull e0 = lds2(rb);
                    ull e1 = lds2(rb + 32);
                    ull e2 = lds2(rb + 64);
                    ull e3 = lds2(rb + 96);
                    ull t0 = fma2(e0, eqp[4*jq+0], ONE2);
                    ull t1 = fma2(e1, eqp[4*jq+1], ONE2);
                    ull t2 = fma2(e2, eqp[4*jq+2], ONE2);
                    ull t3 = fma2(e3, eqp[4*jq+3], ONE2);
                    ull d01 = mul2(t0, t1);
                    ull d23 = mul2(t2, t3);
                    ull n01 = fma2(wep[4*jq+0], t1, mul2(wep[4*jq+1], t0));
                    ull n23 = fma2(wep[4*jq+2], t3, mul2(wep[4*jq+3], t2));
                    ull nQ  = fma2(n01, d23, mul2(n23, d01));
                    ull dQ  = mul2(d01, d23);
                    float da, db; upk(dQ, da, db);
                    acc = fma2(nQ, pk(rcpa(da), rcpa(db)), acc);
                }
                float a0, a1; upk(acc, a0, a1);
                a0 += __shfl_xor_sync(0xffffffffu, a0, 1);
                a1 += __shfl_xor_sync(0xffffffffu, a1, 1);
                a0 += __shfl_xor_sync(0xffffffffu, a0, 2);
                a1 += __shfl_xor_sync(0xffffffffu, a1, 2);
                a0 += __shfl_xor_sync(0xffffffffu, a0, 4);
                a1 += __shfl_xor_sync(0xffffffffu, a1, 4);
                a0 += __shfl_xor_sync(0xffffffffu, a0, 8);
                a1 += __shfl_xor_sync(0xffffffffu, a1, 8);
                if (hc == 0)
                    *(float2*)&srow[2 * t] = make_float2(a0, a1);
            }
        }
    }
}

// ---------------------------------------------------------------------------
// K2b: softmax over k of score = -2*s. Warp per row.
// ---------------------------------------------------------------------------
__global__ __launch_bounds__(256) void softmax_kernel(float* __restrict__ attn)
{
    int row  = blockIdx.x * 8 + (threadIdx.x >> 5);
    int lane = threadIdx.x & 31;
    const float* s = g_s + (size_t)row * LK;

    float vals[16];
    float m = -1e30f;
    #pragma unroll
    for (int i = 0; i < 16; i++) {
        vals[i] = -2.0f * s[lane + 32 * i];
        m = fmaxf(m, vals[i]);
    }
    #pragma unroll
    for (int o = 16; o; o >>= 1) m = fmaxf(m, __shfl_xor_sync(0xffffffffu, m, o));
    float sum = 0.0f;
    #pragma unroll
    for (int i = 0; i < 16; i++) {
        vals[i] = ex2a((vals[i] - m) * 1.4426950408889634f);
        sum += vals[i];
    }
    #pragma unroll
    for (int o = 16; o; o >>= 1) sum += __shfl_xor_sync(0xffffffffu, sum, o);
    float inv = 1.0f / sum;

    float* arow = attn + (size_t)row * LK;
    #pragma unroll
    for (int i = 0; i < 16; i++)
        arow[lane + 32 * i] = vals[i] * inv;
}

// ---------------------------------------------------------------------------
// K3: context partials = attn @ values, split-K2 (64x64 tile, proven 24.3us).
// ---------------------------------------------------------------------------
__global__ __launch_bounds__(256) void context_kernel(
    const float* __restrict__ values, const float* __restrict__ attn)
{
    __shared__ float As[2][32][68];
    __shared__ float Vs[2][32][68];

    int tid = threadIdx.x;
    int b  = blockIdx.z >> 1;
    int ks = blockIdx.z & 1;
    int q0 = blockIdx.x * 64;
    int n0 = blockIdx.y * 64;
    int tx = tid & 15, ty = tid >> 4;
    int kbase = ks * (LK / 2);

    const float* Abase = attn + (size_t)b * LQ * LK + kbase;
    const float* Vbase = values + (size_t)(b * LK + kbase) * HH;

    int arow0 = tid >> 3,         ac40 = tid & 7;
    int arow1 = (tid + 256) >> 3, ac41 = (tid + 256) & 7;
    int vk0 = tid >> 4,           vc40 = tid & 15;
    int vk1 = (tid + 256) >> 4,   vc41 = (tid + 256) & 15;

    float4 ra0, ra1, rv0, rv1;
    ra0 = *(const float4*)&Abase[(size_t)(q0 + arow0) * LK + ac40 * 4];
    ra1 = *(const float4*)&Abase[(size_t)(q0 + arow1) * LK + ac41 * 4];
    rv0 = *(const float4*)&Vbase[(size_t)vk0 * HH + n0 + vc40 * 4];
    rv1 = *(const float4*)&Vbase[(size_t)vk1 * HH + n0 + vc41 * 4];

    As[0][ac40*4+0][arow0] = ra0.x; As[0][ac40*4+1][arow0] = ra0.y;
    As[0][ac40*4+2][arow0] = ra0.z; As[0][ac40*4+3][arow0] = ra0.w;
    As[0][ac41*4+0][arow1] = ra1.x; As[0][ac41*4+1][arow1] = ra1.y;
    As[0][ac41*4+2][arow1] = ra1.z; As[0][ac41*4+3][arow1] = ra1.w;
    *(float4*)&Vs[0][vk0][vc40 * 4] = rv0;
    *(float4*)&Vs[0][vk1][vc41 * 4] = rv1;
    __syncthreads();

    float acc[4][4] = {};
    int buf = 0;

    #pragma unroll 1
    for (int it = 0; it < (LK / 2) / 32; it++) {
        int k1 = (it + 1) * 32;
        bool more = (it + 1 < (LK / 2) / 32);
        if (more) {
            ra0 = *(const float4*)&Abase[(size_t)(q0 + arow0) * LK + k1 + ac40 * 4];
            ra1 = *(const float4*)&Abase[(size_t)(q0 + arow1) * LK + k1 + ac41 * 4];
            rv0 = *(const float4*)&Vbase[(size_t)(k1 + vk0) * HH + n0 + vc40 * 4];
            rv1 = *(const float4*)&Vbase[(size_t)(k1 + vk1) * HH + n0 + vc41 * 4];
        }
        #pragma unroll 8
        for (int kk = 0; kk < 32; kk++) {
            float4 a = *(const float4*)&As[buf][kk][ty * 4];
            float4 v = *(const float4*)&Vs[buf][kk][tx * 4];
            float av[4] = {a.x, a.y, a.z, a.w};
            float vv[4] = {v.x, v.y, v.z, v.w};
            #pragma unroll
            for (int i = 0; i < 4; i++)
                #pragma unroll
                for (int j = 0; j < 4; j++)
                    acc[i][j] = fmaf(av[i], vv[j], acc[i][j]);
        }
        if (more) {
            int nb = buf ^ 1;
            As[nb][ac40*4+0][arow0] = ra0.x; As[nb][ac40*4+1][arow0] = ra0.y;
            As[nb][ac40*4+2][arow0] = ra0.z; As[nb][ac40*4+3][arow0] = ra0.w;
            As[nb][ac41*4+0][arow1] = ra1.x; As[nb][ac41*4+1][arow1] = ra1.y;
            As[nb][ac41*4+2][arow1] = ra1.z; As[nb][ac41*4+3][arow1] = ra1.w;
            *(float4*)&Vs[nb][vk0][vc40 * 4] = rv0;
            *(float4*)&Vs[nb][vk1][vc41 * 4] = rv1;
        }
        __syncthreads();
        buf ^= 1;
    }

    float* part = g_part + (size_t)ks * CTX_ELEMS;
    #pragma unroll
    for (int i = 0; i < 4; i++)
        #pragma unroll
        for (int j = 0; j < 4; j++)
            part[(size_t)(b * LQ + q0 + ty * 4 + i) * HH + n0 + tx * 4 + j] = acc[i][j];
}

// K3b: ctx = part0 + part1
__global__ __launch_bounds__(256) void combine_kernel(float* __restrict__ ctx)
{
    int i = (blockIdx.x * 256 + threadIdx.x) * 4;
    float4 a = *(const float4*)&g_part[i];
    float4 b = *(const float4*)&g_part[CTX_ELEMS + i];
    *(float4*)&ctx[i] = make_float4(a.x + b.x, a.y + b.y, a.z + b.z, a.w + b.w);
}

// ---------------------------------------------------------------------------
// Launch: proj(+exp, K transposed) -> scores -> softmax -> context -> combine.
// Output layout: [context (B*LQ*H) | attention (B*LQ*LK)]. be unused.
// ---------------------------------------------------------------------------
extern "C" void kernel_launch(void* const* d_in, const int* in_sizes, int n_in,
                              void* d_out, int out_size)
{
    const float* query  = (const float*)d_in[0];
    const float* values = (const float*)d_in[1];
    const float* Wq     = (const float*)d_in[2];
    const float* bq     = (const float*)d_in[3];
    const float* Wk     = (const float*)d_in[4];
    const float* bk     = (const float*)d_in[5];
    const float* We     = (const float*)d_in[6];
    // d_in[7] = be, softmax-invariant

    float* out  = (float*)d_out;
    float* ctx  = out;
    float* attn = out + CTX_ELEMS;

    proj_kernel<<<dim3(32, 4, 2), 256>>>(query, values, Wq, bq, Wk, bk);
    score_kernel<<<dim3(LQ / 32, LK / 64, BB), 256>>>(We);
    softmax_kernel<<<dim3(BB * LQ / 8), 256>>>(attn);
    context_kernel<<<dim3(8, 4, BB * 2), 256>>>(values, attn);
    combine_kernel<<<dim3(CTX_ELEMS / 1024), 256>>>(ctx);
}

// round 8
// speedup vs baseline: 1.1154x; 1.0385x over previous
#include <cuda_runtime.h>

#define BB 4
#define LQ 512
#define LK 512
#define HH 256

#define CTX_ELEMS (BB*LQ*HH)
#define LOG2E2 2.885390081777927f   // 2*log2(e)

static __device__ float g_q [BB*LQ*HH];     // Eq = exp(2*q_proj), [b][q][h]
static __device__ float g_kT[BB*HH*LK];     // Ek = exp(2*k_proj), TRANSPOSED [b][h][k]
static __device__ float g_s [BB*LQ*LK];     // raw scores; ref score = C - 2s (consts drop)
static __device__ float g_part[2*CTX_ELEMS];// context split-K partials

typedef unsigned long long ull;

__device__ __forceinline__ float ex2a(float x) {
    float e; asm("ex2.approx.ftz.f32 %0, %1;" : "=f"(e) : "f"(x)); return e;
}
__device__ __forceinline__ float rcpa(float x) {
    float r; asm("rcp.approx.ftz.f32 %0, %1;" : "=f"(r) : "f"(x)); return r;
}
__device__ __forceinline__ ull pk(float x, float y) {
    ull r; asm("mov.b64 %0, {%1, %2};" : "=l"(r) : "f"(x), "f"(y)); return r;
}
__device__ __forceinline__ void upk(ull v, float& x, float& y) {
    asm("mov.b64 {%0, %1}, %2;" : "=f"(x), "=f"(y) : "l"(v));
}
__device__ __forceinline__ ull fma2(ull a, ull b, ull c) {
    ull d; asm("fma.rn.f32x2 %0, %1, %2, %3;" : "=l"(d) : "l"(a), "l"(b), "l"(c)); return d;
}
__device__ __forceinline__ ull mul2(ull a, ull b) {
    ull d; asm("mul.rn.f32x2 %0, %1, %2;" : "=l"(d) : "l"(a), "l"(b)); return d;
}
__device__ __forceinline__ ull add2(ull a, ull b) {
    ull d; asm("add.rn.f32x2 %0, %1, %2;" : "=l"(d) : "l"(a), "l"(b)); return d;
}
__device__ __forceinline__ ull lds2(const float* p) {
    return *(const ull*)p;
}

// ---------------------------------------------------------------------------
// K1: projections + exp epilogue. Double-buffered smem + register prefetch.
// Inner loop: packed f32x2 (8 FFMA2 per kk instead of 16 FFMA).
// z=0: g_q[b][q][h] = exp(2*(q@WqT+bq));  z=1: g_kT[b][h][k] (transposed!)
// ---------------------------------------------------------------------------
__global__ __launch_bounds__(256) void proj_kernel(
    const float* __restrict__ query, const float* __restrict__ values,
    const float* __restrict__ Wq, const float* __restrict__ bq,
    const float* __restrict__ Wk, const float* __restrict__ bk)
{
    const float* in   = blockIdx.z ? values : query;
    const float* W    = blockIdx.z ? Wk : Wq;
    const float* bias = blockIdx.z ? bk : bq;

    __shared__ float As[2][32][68];
    __shared__ float Bs[2][32][68];

    int tid = threadIdx.x;
    int tx = tid & 15, ty = tid >> 4;
    int m0 = blockIdx.x * 64, n0 = blockIdx.y * 64;

    int row0 = tid >> 3,         c40 = tid & 7;
    int row1 = (tid + 256) >> 3, c41 = (tid + 256) & 7;

    float4 ra0, ra1, rb0, rb1;
    ra0 = *(const float4*)&in[(size_t)(m0 + row0) * HH + c40 * 4];
    rb0 = *(const float4*)&W [(size_t)(n0 + row0) * HH + c40 * 4];
    ra1 = *(const float4*)&in[(size_t)(m0 + row1) * HH + c41 * 4];
    rb1 = *(const float4*)&W [(size_t)(n0 + row1) * HH + c41 * 4];

    As[0][c40*4+0][row0] = ra0.x; As[0][c40*4+1][row0] = ra0.y;
    As[0][c40*4+2][row0] = ra0.z; As[0][c40*4+3][row0] = ra0.w;
    Bs[0][c40*4+0][row0] = rb0.x; Bs[0][c40*4+1][row0] = rb0.y;
    Bs[0][c40*4+2][row0] = rb0.z; Bs[0][c40*4+3][row0] = rb0.w;
    As[0][c41*4+0][row1] = ra1.x; As[0][c41*4+1][row1] = ra1.y;
    As[0][c41*4+2][row1] = ra1.z; As[0][c41*4+3][row1] = ra1.w;
    Bs[0][c41*4+0][row1] = rb1.x; Bs[0][c41*4+1][row1] = rb1.y;
    Bs[0][c41*4+2][row1] = rb1.z; Bs[0][c41*4+3][row1] = rb1.w;
    __syncthreads();

    ull acc2[4][2] = {};   // [m][n-pair], packed over n
    int buf = 0;

    #pragma unroll 1
    for (int it = 0; it < HH / 32; it++) {
        int k1 = (it + 1) * 32;
        bool more = (it + 1 < HH / 32);
        if (more) {
            ra0 = *(const float4*)&in[(size_t)(m0 + row0) * HH + k1 + c40 * 4];
            rb0 = *(const float4*)&W [(size_t)(n0 + row0) * HH + k1 + c40 * 4];
            ra1 = *(const float4*)&in[(size_t)(m0 + row1) * HH + k1 + c41 * 4];
            rb1 = *(const float4*)&W [(size_t)(n0 + row1) * HH + k1 + c41 * 4];
        }
        #pragma unroll 8
        for (int kk = 0; kk < 32; kk++) {
            float4 a = *(const float4*)&As[buf][kk][ty * 4];
            ulonglong2 b = *(const ulonglong2*)&Bs[buf][kk][tx * 4];
            ull a0 = pk(a.x, a.x), a1 = pk(a.y, a.y);
            ull a2 = pk(a.z, a.z), a3 = pk(a.w, a.w);
            acc2[0][0] = fma2(a0, b.x, acc2[0][0]);
            acc2[0][1] = fma2(a0, b.y, acc2[0][1]);
            acc2[1][0] = fma2(a1, b.x, acc2[1][0]);
            acc2[1][1] = fma2(a1, b.y, acc2[1][1]);
            acc2[2][0] = fma2(a2, b.x, acc2[2][0]);
            acc2[2][1] = fma2(a2, b.y, acc2[2][1]);
            acc2[3][0] = fma2(a3, b.x, acc2[3][0]);
            acc2[3][1] = fma2(a3, b.y, acc2[3][1]);
        }
        if (more) {
            int nb = buf ^ 1;
            As[nb][c40*4+0][row0] = ra0.x; As[nb][c40*4+1][row0] = ra0.y;
            As[nb][c40*4+2][row0] = ra0.z; As[nb][c40*4+3][row0] = ra0.w;
            Bs[nb][c40*4+0][row0] = rb0.x; Bs[nb][c40*4+1][row0] = rb0.y;
            Bs[nb][c40*4+2][row0] = rb0.z; Bs[nb][c40*4+3][row0] = rb0.w;
            As[nb][c41*4+0][row1] = ra1.x; As[nb][c41*4+1][row1] = ra1.y;
            As[nb][c41*4+2][row1] = ra1.z; As[nb][c41*4+3][row1] = ra1.w;
            Bs[nb][c41*4+0][row1] = rb1.x; Bs[nb][c41*4+1][row1] = rb1.y;
            Bs[nb][c41*4+2][row1] = rb1.z; Bs[nb][c41*4+3][row1] = rb1.w;
        }
        __syncthreads();
        buf ^= 1;
    }

    float acc[4][4];
    #pragma unroll
    for (int i = 0; i < 4; i++) {
        upk(acc2[i][0], acc[i][0], acc[i][1]);
        upk(acc2[i][1], acc[i][2], acc[i][3]);
    }

    if (blockIdx.z == 0) {
        #pragma unroll
        for (int i = 0; i < 4; i++)
            #pragma unroll
            for (int j = 0; j < 4; j++) {
                int m = m0 + ty * 4 + i;
                int n = n0 + tx * 4 + j;
                g_q[(size_t)m * HH + n] = ex2a((acc[i][j] + bias[n]) * LOG2E2);
            }
    } else {
        int b    = m0 / LK;
        int mloc = (m0 % LK) + ty * 4;
        #pragma unroll
        for (int j = 0; j < 4; j++) {
            int n = n0 + tx * 4 + j;
            float4 v;
            v.x = ex2a((acc[0][j] + bias[n]) * LOG2E2);
            v.y = ex2a((acc[1][j] + bias[n]) * LOG2E2);
            v.z = ex2a((acc[2][j] + bias[n]) * LOG2E2);
            v.w = ex2a((acc[3][j] + bias[n]) * LOG2E2);
            *(float4*)&g_kT[((size_t)b * HH + n) * LK + mloc] = v;
        }
    }
}

// ---------------------------------------------------------------------------
// K2: scores, packed f32x2 quad-rcp, h-contiguous coalesced eq/We loads,
// XOR-swizzled ek smem (conflict-free LDS.64). Dual accumulators (even/odd
// quad) halve the serial acc chain; unroll 4 on the k-pair loop for ILP.
// ---------------------------------------------------------------------------
__global__ __launch_bounds__(256) void score_kernel(const float* __restrict__ We)
{
    __shared__ float eks[256][32];   // 32 KB, swizzled

    int b  = blockIdx.z;
    int q0 = blockIdx.x * 32;
    int k0 = blockIdx.y * 64;
    int tid  = threadIdx.x;
    int lane = tid & 31;
    int hc   = lane & 15;
    int qh   = lane >> 4;
    int w    = tid >> 5;

    int s_kp = tid & 15;     // staging: kpair
    int s_hh = tid >> 4;     // staging: h mod 16

    const ull ONE2 = pk(1.0f, 1.0f);

    ull wep[16];
    {
        const float4* wp = (const float4*)(We + hc * 16);
        float4 w0 = wp[0], w1 = wp[1], w2 = wp[2], w3 = wp[3];
        wep[0]=pk(w0.x,w0.x); wep[1]=pk(w0.y,w0.y); wep[2]=pk(w0.z,w0.z); wep[3]=pk(w0.w,w0.w);
        wep[4]=pk(w1.x,w1.x); wep[5]=pk(w1.y,w1.y); wep[6]=pk(w1.z,w1.z); wep[7]=pk(w1.w,w1.w);
        wep[8]=pk(w2.x,w2.x); wep[9]=pk(w2.y,w2.y); wep[10]=pk(w2.z,w2.z); wep[11]=pk(w2.w,w2.w);
        wep[12]=pk(w3.x,w3.x); wep[13]=pk(w3.y,w3.y); wep[14]=pk(w3.z,w3.z); wep[15]=pk(w3.w,w3.w);
    }

    #pragma unroll 1
    for (int st = 0; st < 2; st++) {
        int kb = k0 + st * 32;
        __syncthreads();
        #pragma unroll
        for (int i = 0; i < 16; i++) {
            int h = s_hh + 16 * i;
            ull v = *(const ull*)(g_kT + ((size_t)(b * HH + h)) * LK + kb + 2 * s_kp);
            *(ull*)&eks[h][(s_kp ^ i) * 2] = v;
        }
        __syncthreads();

        #pragma unroll 1
        for (int qp = 0; qp < 2; qp++) {
            int q = q0 + qp * 16 + w * 2 + qh;
            ull eqp[16];
            {
                const float4* ep = (const float4*)(g_q + ((size_t)(b * LQ) + q) * HH + hc * 16);
                float4 e0 = ep[0], e1 = ep[1], e2 = ep[2], e3 = ep[3];
                eqp[0]=pk(e0.x,e0.x); eqp[1]=pk(e0.y,e0.y); eqp[2]=pk(e0.z,e0.z); eqp[3]=pk(e0.w,e0.w);
                eqp[4]=pk(e1.x,e1.x); eqp[5]=pk(e1.y,e1.y); eqp[6]=pk(e1.z,e1.z); eqp[7]=pk(e1.w,e1.w);
                eqp[8]=pk(e2.x,e2.x); eqp[9]=pk(e2.y,e2.y); eqp[10]=pk(e2.z,e2.z); eqp[11]=pk(e2.w,e2.w);
                eqp[12]=pk(e3.x,e3.x); eqp[13]=pk(e3.y,e3.y); eqp[14]=pk(e3.z,e3.z); eqp[15]=pk(e3.w,e3.w);
            }
            float* srow = g_s + ((size_t)(b * LQ) + q) * LK + kb;

            #pragma unroll 4
            for (int t = 0; t < 16; t++) {
                int pc = (t ^ hc) * 2;
                ull accE = 0ull, accO = 0ull;   // 0 bits == (0.0f, 0.0f)
                #pragma unroll
                for (int jq = 0; jq < 4; jq++) {
                    const float* rb = &eks[16 * hc + 4 * jq][pc];
                    ull e0 = lds2(rb);
                    ull e1 = lds2(rb + 32);
                    ull e2 = lds2(rb + 64);
                    ull e3 = lds2(rb + 96);
                    ull t0 = fma2(e0, eqp[4*jq+0], ONE2);
                    ull t1 = fma2(e1, eqp[4*jq+1], ONE2);
                    ull t2 = fma2(e2, eqp[4*jq+2], ONE2);
                    ull t3 = fma2(e3, eqp[4*jq+3], ONE2);
                    ull d01 = mul2(t0, t1);
                    ull d23 = mul2(t2, t3);
                    ull n01 = fma2(wep[4*jq+0], t1, mul2(wep[4*jq+1], t0));
                    ull n23 = fma2(wep[4*jq+2], t3, mul2(wep[4*jq+3], t2));
                    ull nQ  = fma2(n01, d23, mul2(n23, d01));
                    ull dQ  = mul2(d01, d23);
                    float da, db; upk(dQ, da, db);
                    ull rp = pk(rcpa(da), rcpa(db));
                    if (jq & 1) accO = fma2(nQ, rp, accO);
                    else        accE = fma2(nQ, rp, accE);
                }
                ull accT = add2(accE, accO);
                float a0, a1; upk(accT, a0, a1);
                a0 += __shfl_xor_sync(0xffffffffu, a0, 1);
                a1 += __shfl_xor_sync(0xffffffffu, a1, 1);
                a0 += __shfl_xor_sync(0xffffffffu, a0, 2);
                a1 += __shfl_xor_sync(0xffffffffu, a1, 2);
                a0 += __shfl_xor_sync(0xffffffffu, a0, 4);
                a1 += __shfl_xor_sync(0xffffffffu, a1, 4);
                a0 += __shfl_xor_sync(0xffffffffu, a0, 8);
                a1 += __shfl_xor_sync(0xffffffffu, a1, 8);
                if (hc == 0)
                    *(float2*)&srow[2 * t] = make_float2(a0, a1);
            }
        }
    }
}

// ---------------------------------------------------------------------------
// K2b: softmax over k of score = -2*s. Warp per row.
// ---------------------------------------------------------------------------
__global__ __launch_bounds__(256) void softmax_kernel(float* __restrict__ attn)
{
    int row  = blockIdx.x * 8 + (threadIdx.x >> 5);
    int lane = threadIdx.x & 31;
    const float* s = g_s + (size_t)row * LK;

    float vals[16];
    float m = -1e30f;
    #pragma unroll
    for (int i = 0; i < 16; i++) {
        vals[i] = -2.0f * s[lane + 32 * i];
        m = fmaxf(m, vals[i]);
    }
    #pragma unroll
    for (int o = 16; o; o >>= 1) m = fmaxf(m, __shfl_xor_sync(0xffffffffu, m, o));
    float sum = 0.0f;
    #pragma unroll
    for (int i = 0; i < 16; i++) {
        vals[i] = ex2a((vals[i] - m) * 1.4426950408889634f);
        sum += vals[i];
    }
    #pragma unroll
    for (int o = 16; o; o >>= 1) sum += __shfl_xor_sync(0xffffffffu, sum, o);
    float inv = 1.0f / sum;

    float* arow = attn + (size_t)row * LK;
    #pragma unroll
    for (int i = 0; i < 16; i++)
        arow[lane + 32 * i] = vals[i] * inv;
}

// ---------------------------------------------------------------------------
// K3: context partials = attn @ values, split-K2, packed f32x2 inner.
// ---------------------------------------------------------------------------
__global__ __launch_bounds__(256) void context_kernel(
    const float* __restrict__ values, const float* __restrict__ attn)
{
    __shared__ float As[2][32][68];
    __shared__ float Vs[2][32][68];

    int tid = threadIdx.x;
    int b  = blockIdx.z >> 1;
    int ks = blockIdx.z & 1;
    int q0 = blockIdx.x * 64;
    int n0 = blockIdx.y * 64;
    int tx = tid & 15, ty = tid >> 4;
    int kbase = ks * (LK / 2);

    const float* Abase = attn + (size_t)b * LQ * LK + kbase;
    const float* Vbase = values + (size_t)(b * LK + kbase) * HH;

    int arow0 = tid >> 3,         ac40 = tid & 7;
    int arow1 = (tid + 256) >> 3, ac41 = (tid + 256) & 7;
    int vk0 = tid >> 4,           vc40 = tid & 15;
    int vk1 = (tid + 256) >> 4,   vc41 = (tid + 256) & 15;

    float4 ra0, ra1, rv0, rv1;
    ra0 = *(const float4*)&Abase[(size_t)(q0 + arow0) * LK + ac40 * 4];
    ra1 = *(const float4*)&Abase[(size_t)(q0 + arow1) * LK + ac41 * 4];
    rv0 = *(const float4*)&Vbase[(size_t)vk0 * HH + n0 + vc40 * 4];
    rv1 = *(const float4*)&Vbase[(size_t)vk1 * HH + n0 + vc41 * 4];

    As[0][ac40*4+0][arow0] = ra0.x; As[0][ac40*4+1][arow0] = ra0.y;
    As[0][ac40*4+2][arow0] = ra0.z; As[0][ac40*4+3][arow0] = ra0.w;
    As[0][ac41*4+0][arow1] = ra1.x; As[0][ac41*4+1][arow1] = ra1.y;
    As[0][ac41*4+2][arow1] = ra1.z; As[0][ac41*4+3][arow1] = ra1.w;
    *(float4*)&Vs[0][vk0][vc40 * 4] = rv0;
    *(float4*)&Vs[0][vk1][vc41 * 4] = rv1;
    __syncthreads();

    ull acc2[4][2] = {};
    int buf = 0;

    #pragma unroll 1
    for (int it = 0; it < (LK / 2) / 32; it++) {
        int k1 = (it + 1) * 32;
        bool more = (it + 1 < (LK / 2) / 32);
        if (more) {
            ra0 = *(const float4*)&Abase[(size_t)(q0 + arow0) * LK + k1 + ac40 * 4];
            ra1 = *(const float4*)&Abase[(size_t)(q0 + arow1) * LK + k1 + ac41 * 4];
            rv0 = *(const float4*)&Vbase[(size_t)(k1 + vk0) * HH + n0 + vc40 * 4];
            rv1 = *(const float4*)&Vbase[(size_t)(k1 + vk1) * HH + n0 + vc41 * 4];
        }
        #pragma unroll 8
        for (int kk = 0; kk < 32; kk++) {
            float4 a = *(const float4*)&As[buf][kk][ty * 4];
            ulonglong2 v = *(const ulonglong2*)&Vs[buf][kk][tx * 4];
            ull a0 = pk(a.x, a.x), a1 = pk(a.y, a.y);
            ull a2 = pk(a.z, a.z), a3 = pk(a.w, a.w);
            acc2[0][0] = fma2(a0, v.x, acc2[0][0]);
            acc2[0][1] = fma2(a0, v.y, acc2[0][1]);
            acc2[1][0] = fma2(a1, v.x, acc2[1][0]);
            acc2[1][1] = fma2(a1, v.y, acc2[1][1]);
            acc2[2][0] = fma2(a2, v.x, acc2[2][0]);
            acc2[2][1] = fma2(a2, v.y, acc2[2][1]);
            acc2[3][0] = fma2(a3, v.x, acc2[3][0]);
            acc2[3][1] = fma2(a3, v.y, acc2[3][1]);
        }
        if (more) {
            int nb = buf ^ 1;
            As[nb][ac40*4+0][arow0] = ra0.x; As[nb][ac40*4+1][arow0] = ra0.y;
            As[nb][ac40*4+2][arow0] = ra0.z; As[nb][ac40*4+3][arow0] = ra0.w;
            As[nb][ac41*4+0][arow1] = ra1.x; As[nb][ac41*4+1][arow1] = ra1.y;
            As[nb][ac41*4+2][arow1] = ra1.z; As[nb][ac41*4+3][arow1] = ra1.w;
            *(float4*)&Vs[nb][vk0][vc40 * 4] = rv0;
            *(float4*)&Vs[nb][vk1][vc41 * 4] = rv1;
        }
        __syncthreads();
        buf ^= 1;
    }

    float* part = g_part + (size_t)ks * CTX_ELEMS;
    #pragma unroll
    for (int i = 0; i < 4; i++) {
        float4 r;
        upk(acc2[i][0], r.x, r.y);
        upk(acc2[i][1], r.z, r.w);
        *(float4*)&part[(size_t)(b * LQ + q0 + ty * 4 + i) * HH + n0 + tx * 4] = r;
    }
}

// K3b: ctx = part0 + part1
__global__ __launch_bounds__(256) void combine_kernel(float* __restrict__ ctx)
{
    int i = (blockIdx.x * 256 + threadIdx.x) * 4;
    float4 a = *(const float4*)&g_part[i];
    float4 b = *(const float4*)&g_part[CTX_ELEMS + i];
    *(float4*)&ctx[i] = make_float4(a.x + b.x, a.y + b.y, a.z + b.z, a.w + b.w);
}

// ---------------------------------------------------------------------------
// Launch: proj(+exp, K transposed) -> scores -> softmax -> context -> combine.
// Output layout: [context (B*LQ*H) | attention (B*LQ*LK)]. be unused.
// ---------------------------------------------------------------------------
extern "C" void kernel_launch(void* const* d_in, const int* in_sizes, int n_in,
                              void* d_out, int out_size)
{
    const float* query  = (const float*)d_in[0];
    const float* values = (const float*)d_in[1];
    const float* Wq     = (const float*)d_in[2];
    const float* bq     = (const float*)d_in[3];
    const float* Wk     = (const float*)d_in[4];
    const float* bk     = (const float*)d_in[5];
    const float* We     = (const float*)d_in[6];
    // d_in[7] = be, softmax-invariant

    float* out  = (float*)d_out;
    float* ctx  = out;
    float* attn = out + CTX_ELEMS;

    proj_kernel<<<dim3(32, 4, 2), 256>>>(query, values, Wq, bq, Wk, bk);
    score_kernel<<<dim3(LQ / 32, LK / 64, BB), 256>>>(We);
    softmax_kernel<<<dim3(BB * LQ / 8), 256>>>(attn);
    context_kernel<<<dim3(8, 4, BB * 2), 256>>>(values, attn);
    combine_kernel<<<dim3(CTX_ELEMS / 1024), 256>>>(ctx);
}